// round 7
// baseline (speedup 1.0000x reference)
#include <cuda_runtime.h>

// ---------------------------------------------------------------------------
// Decoder step: attention (B=128, L=2048, H=256) + 2x LSTM cell.
//
// attn_kernel : split-K flash softmax, grid = 128 x 4 splits (HBM-bound,
//               runs alone so all SM slots stream encoder_outputs).
// fused_mid   : grid 384, independent blocks:
//                 0-127   gates1 = bias1 + hidden1 @ w_hh1^T      (K=256)
//                 128-255 gates2 = bias2 + embed @ w_ih2[:,:256]^T
//                                        + hidden2 @ w_hh2^T      (K=512)
//                 256-383 combine 4 attn splits -> g_ctxT
//               gate blocks use a register-prefetch pipeline.
// finish<1>   : gates1 += ctx @ w_ih1^T, epilogue -> h1,c1, g_h1T.
// finish<2>   : gates2 += h1 @ w_ih2[:,256:]^T, epilogue -> out,h2,c2.
//               finish: grid=256 (1 h/block), warps split K 8-ways, X via
//               pipelined LDG.128 (prefetch next batch during FMA).
// ---------------------------------------------------------------------------

#define B_ 128
#define H_ 256
#define L_ 2048
#define NSPLIT 4
#define LSP (L_ / NSPLIT)
#define ATTN_BLOCKS (B_ * NSPLIT)   // 512

__device__ float g_ctxT[256 * 128];
__device__ float g_h1T[256 * 128];
__device__ float g_gates1[1024 * 128];
__device__ float g_gates2[1024 * 128];
__device__ float g_ctx_part[B_ * NSPLIT * H_];
__device__ float g_md[B_ * NSPLIT * 2];

// ---------------- helpers ----------------------------------------------------

__device__ __forceinline__ void online_step(
    const float4& ea, const float4& eb, const float4& ha, const float4& hb,
    float& m, float& d, float* c)
{
    float s = ea.x * ha.x + ea.y * ha.y + ea.z * ha.z + ea.w * ha.w
            + eb.x * hb.x + eb.y * hb.y + eb.z * hb.z + eb.w * hb.w;
#pragma unroll
    for (int off = 16; off; off >>= 1)
        s += __shfl_xor_sync(0xffffffffu, s, off);
    float mn = fmaxf(m, s);
    float es = __expf(s - mn);
    float em = __expf(m - mn);
    d = d * em + es;
    c[0] = fmaf(c[0], em, es * ea.x);
    c[1] = fmaf(c[1], em, es * ea.y);
    c[2] = fmaf(c[2], em, es * ea.z);
    c[3] = fmaf(c[3], em, es * ea.w);
    c[4] = fmaf(c[4], em, es * eb.x);
    c[5] = fmaf(c[5], em, es * eb.y);
    c[6] = fmaf(c[6], em, es * eb.z);
    c[7] = fmaf(c[7], em, es * eb.w);
    m = mn;
}

__device__ __forceinline__ float sigmoidf_(float x) {
    return 1.f / (1.f + __expf(-x));
}

__device__ __forceinline__ void cp_async16(void* smem_dst, const void* gmem_src) {
    unsigned saddr = (unsigned)__cvta_generic_to_shared(smem_dst);
    asm volatile("cp.async.cg.shared.global [%0], [%1], 16;\n"
                 :: "r"(saddr), "l"(gmem_src));
}
__device__ __forceinline__ void cp_commit() {
    asm volatile("cp.async.commit_group;\n");
}
__device__ __forceinline__ void cp_wait0() {
    asm volatile("cp.async.wait_group 0;\n");
}

// ---------------- attention ----------------------------------------------------

__global__ __launch_bounds__(256, 2) void attn_kernel(
    const float* __restrict__ enc,
    const float* __restrict__ hidden1)
{
    const int bx   = blockIdx.x;
    const int tid  = threadIdx.x;
    const int w    = tid >> 5;
    const int lane = tid & 31;

    const int b  = bx >> 2;
    const int sp = bx & 3;

    __shared__ float h1s[H_];
    __shared__ float ctx_s[8][H_];
    __shared__ float m_s[8], d_s[8];

    h1s[tid] = hidden1[b * H_ + tid];
    __syncthreads();

    const float4 ha = *reinterpret_cast<const float4*>(&h1s[lane * 4]);
    const float4 hb = *reinterpret_cast<const float4*>(&h1s[128 + lane * 4]);

    const float* encb = enc + (size_t)b * (L_ * H_) + (size_t)sp * (LSP * H_);

    float m[4], d[4], c[4][8];
    float4 ea[4], eb[4];
    const float* p[4];
#pragma unroll
    for (int j = 0; j < 4; j++) {
        m[j] = -1e30f; d[j] = 0.f;
#pragma unroll
        for (int q = 0; q < 8; q++) c[j][q] = 0.f;
        p[j]  = encb + (size_t)(w + 8 * j) * H_ + lane * 4;
        ea[j] = *reinterpret_cast<const float4*>(p[j]);
        eb[j] = *reinterpret_cast<const float4*>(p[j] + 128);
    }

    const int STRIDE = 32 * H_;
    const int ITERS  = LSP / 32;
    for (int i = 0; i < ITERS - 1; i++) {
        float4 na[4], nb[4];
#pragma unroll
        for (int j = 0; j < 4; j++) {
            na[j] = *reinterpret_cast<const float4*>(p[j] + STRIDE);
            nb[j] = *reinterpret_cast<const float4*>(p[j] + STRIDE + 128);
        }
#pragma unroll
        for (int j = 0; j < 4; j++)
            online_step(ea[j], eb[j], ha, hb, m[j], d[j], c[j]);
#pragma unroll
        for (int j = 0; j < 4; j++) {
            ea[j] = na[j]; eb[j] = nb[j]; p[j] += STRIDE;
        }
    }
#pragma unroll
    for (int j = 0; j < 4; j++)
        online_step(ea[j], eb[j], ha, hb, m[j], d[j], c[j]);

#pragma unroll
    for (int j = 1; j < 4; j++) {
        float M2 = fmaxf(m[0], m[j]);
        float e0 = __expf(m[0] - M2);
        float e1 = __expf(m[j] - M2);
        d[0] = d[0] * e0 + d[j] * e1;
#pragma unroll
        for (int q = 0; q < 8; q++)
            c[0][q] = c[0][q] * e0 + c[j][q] * e1;
        m[0] = M2;
    }

#pragma unroll
    for (int q = 0; q < 4; q++) {
        ctx_s[w][lane * 4 + q]       = c[0][q];
        ctx_s[w][128 + lane * 4 + q] = c[0][4 + q];
    }
    if (lane == 0) { m_s[w] = m[0]; d_s[w] = d[0]; }
    __syncthreads();

    float M = m_s[0];
#pragma unroll
    for (int ww = 1; ww < 8; ww++) M = fmaxf(M, m_s[ww]);
    float D = 0.f, C = 0.f;
#pragma unroll
    for (int ww = 0; ww < 8; ww++) {
        float e = __expf(m_s[ww] - M);
        D += d_s[ww] * e;
        C += ctx_s[ww][tid] * e;
    }
    g_ctx_part[bx * H_ + tid] = C;
    if (tid == 0) { g_md[bx * 2] = M; g_md[bx * 2 + 1] = D; }
}

// ---------------- fused mid: gates1 | gates2 | combine -------------------------

__global__ __launch_bounds__(256, 2) void fused_mid(
    const float* __restrict__ hidden1,
    const float* __restrict__ embed,
    const float* __restrict__ hidden2,
    const float* __restrict__ w_hh1,
    const float* __restrict__ w_ih2,
    const float* __restrict__ w_hh2,
    const float* __restrict__ b_ih1, const float* __restrict__ b_hh1,
    const float* __restrict__ b_ih2, const float* __restrict__ b_hh2)
{
    extern __shared__ float smem_f[];   // Ws[8*512] + Xs[64*128] = 48 KB
    const int bid  = blockIdx.x;
    const int tid  = threadIdx.x;
    const int warp = tid >> 5;
    const int lane = tid & 31;

    if (bid >= 256) {
        // ---------------- combine block ----------------
        const int b = bid - 256;
        const int h = tid;
        float ms[NSPLIT], ds[NSPLIT];
#pragma unroll
        for (int s = 0; s < NSPLIT; s++) {
            ms[s] = g_md[(b * NSPLIT + s) * 2];
            ds[s] = g_md[(b * NSPLIT + s) * 2 + 1];
        }
        float M = ms[0];
#pragma unroll
        for (int s = 1; s < NSPLIT; s++) M = fmaxf(M, ms[s]);
        float D = 0.f, C = 0.f;
#pragma unroll
        for (int s = 0; s < NSPLIT; s++) {
            float e = __expf(ms[s] - M);
            D += ds[s] * e;
            C += g_ctx_part[(b * NSPLIT + s) * H_ + h] * e;
        }
        g_ctxT[h * B_ + b] = C / D;
        return;
    }

    // ---------------- gate block ----------------
    const bool is2 = (bid >= 128);
    const int  gb  = is2 ? bid - 128 : bid;
    const int  h0  = gb * 2;
    const int  KP  = is2 ? 512 : 256;

    float* Ws = smem_f;                  // [8][KP]
    float* Xs = smem_f + 8 * 512;        // [64][128]

    const int b0 = lane * 4;
    const int bb = tid & 127;
    const int kh = (tid >> 7) * 32;

    // W preload (coalesced over k)
    const int K4 = KP / 4;
    for (int idx = tid; idx < 8 * K4; idx += 256) {
        int r = idx / K4;
        int k = (idx - r * K4) * 4;
        int grow = (r & 3) * H_ + h0 + (r >> 2);
        float4 v;
        if (!is2) {
            v = *reinterpret_cast<const float4*>(&w_hh1[(size_t)grow * 256 + k]);
        } else if (k < 256) {
            v = *reinterpret_cast<const float4*>(&w_ih2[(size_t)grow * 512 + k]);
        } else {
            v = *reinterpret_cast<const float4*>(&w_hh2[(size_t)grow * 256 + (k - 256)]);
        }
        *reinterpret_cast<float4*>(&Ws[r * KP + k]) = v;
    }

    float acc[4][8];
#pragma unroll
    for (int j = 0; j < 4; j++)
#pragma unroll
        for (int r = 0; r < 8; r++) acc[j][r] = 0.f;

    const int NCH = KP / 64;

    // helper to fetch this thread's 32-k slab of chunk c into registers
    auto src_of = [&](int c) -> const float* {
        const int kb = c * 64 + kh;
        if (!is2)          return hidden1 + bb * H_ + kb;
        else if (kb < 256) return embed   + bb * H_ + kb;
        else               return hidden2 + bb * H_ + (kb - 256);
    };

    float4 vreg[8];
    {
        const float* src = src_of(0);
#pragma unroll
        for (int i = 0; i < 8; i++)
            vreg[i] = *reinterpret_cast<const float4*>(src + i * 4);
    }

    for (int c = 0; c < NCH; c++) {
        __syncthreads();      // Xs free (also orders Ws on first iter)
#pragma unroll
        for (int i = 0; i < 8; i++) {
            int kl = kh + i * 4;
            Xs[(kl + 0) * 128 + bb] = vreg[i].x;
            Xs[(kl + 1) * 128 + bb] = vreg[i].y;
            Xs[(kl + 2) * 128 + bb] = vreg[i].z;
            Xs[(kl + 3) * 128 + bb] = vreg[i].w;
        }
        __syncthreads();

        if (c + 1 < NCH) {
            const float* src = src_of(c + 1);
#pragma unroll
            for (int i = 0; i < 8; i++)
                vreg[i] = *reinterpret_cast<const float4*>(src + i * 4);
        }

        const float* xb = Xs + (warp * 8) * 128;
        const int kg = c * 64 + warp * 8;
#pragma unroll
        for (int g2 = 0; g2 < 2; g2++) {
            float4 xv[4];
#pragma unroll
            for (int kk = 0; kk < 4; kk++)
                xv[kk] = *reinterpret_cast<const float4*>(
                    &xb[(g2 * 4 + kk) * 128 + b0]);
            float wv[8][4];
#pragma unroll
            for (int r = 0; r < 8; r++)
                *reinterpret_cast<float4*>(wv[r]) =
                    *reinterpret_cast<const float4*>(&Ws[r * KP + kg + g2 * 4]);
#pragma unroll
            for (int kk = 0; kk < 4; kk++) {
#pragma unroll
                for (int r = 0; r < 8; r++) {
                    acc[0][r] = fmaf(xv[kk].x, wv[r][kk], acc[0][r]);
                    acc[1][r] = fmaf(xv[kk].y, wv[r][kk], acc[1][r]);
                    acc[2][r] = fmaf(xv[kk].z, wv[r][kk], acc[2][r]);
                    acc[3][r] = fmaf(xv[kk].w, wv[r][kk], acc[3][r]);
                }
            }
        }
    }

    __syncthreads();
#pragma unroll
    for (int r = 0; r < 8; r++)
#pragma unroll
        for (int j = 0; j < 4; j++)
            Xs[r * 1024 + warp * 128 + b0 + j] = acc[j][r];
    __syncthreads();

    float* gg = is2 ? g_gates2 : g_gates1;
    const float* bi = is2 ? b_ih2 : b_ih1;
    const float* bh = is2 ? b_hh2 : b_hh1;
    for (int e = tid; e < 1024; e += 256) {
        int r = e >> 7, b = e & 127;
        float s = 0.f;
#pragma unroll
        for (int w = 0; w < 8; w++)
            s += Xs[r * 1024 + w * 128 + b];
        int grow = (r & 3) * H_ + h0 + (r >> 2);
        gg[grow * 128 + b] = s + bi[grow] + bh[grow];
    }
}

// ---------------- finish: dependent K=256 GEMM + epilogue ----------------------

// Block = 1 h-index (4 gate rows) x 128 batches. grid = 256.
// Warps split K 8-ways (32 k each), pipelined LDG.128 for X.
template <int LAYER>
__global__ __launch_bounds__(256, 2) void finish_kernel(
    const float* __restrict__ w_ih,      // L1: w_ih1 ; L2: w_ih2
    const float* __restrict__ c_prev,
    float* __restrict__ out)
{
    constexpr int RS  = (LAYER == 1) ? 256 : 512;   // w row stride
    constexpr int OFF = (LAYER == 1) ? 0 : 256;     // col offset

    __shared__ float Ws[4 * 256];        // 4 gate rows x 256 k
    __shared__ float Rs[4 * 8 * 128];    // [gate][warp][batch]

    const int tid  = threadIdx.x;
    const int warp = tid >> 5;
    const int lane = tid & 31;
    const int b0   = lane * 4;
    const int h    = blockIdx.x;

    const float* __restrict__ XT = (LAYER == 1) ? g_ctxT : g_h1T;
    const float* __restrict__ GG = (LAYER == 1) ? g_gates1 : g_gates2;

    const int kbase = warp * 32;

    // prefetch epilogue operands early (in flight during mainloop)
    float ggv[4];
    float cpv = 0.f;
    if (tid < 128) {
#pragma unroll
        for (int g = 0; g < 4; g++)
            ggv[g] = GG[(size_t)(g * H_ + h) * 128 + tid];
        cpv = c_prev[tid * H_ + h];
    }

    // issue s=0 X loads before W prologue
    float4 xv[8], xn[8];
#pragma unroll
    for (int i = 0; i < 8; i++)
        xv[i] = *reinterpret_cast<const float4*>(
            &XT[(size_t)(kbase + i) * 128 + b0]);

    // W prologue: 4 rows x 64 float4 = 256 transfers, one per thread
    {
        int g  = tid >> 6;
        int k4 = tid & 63;
        cp_async16(&Ws[g * 256 + k4 * 4],
                   w_ih + (size_t)(g * H_ + h) * RS + OFF + k4 * 4);
        cp_commit();
        cp_wait0();
    }
    __syncthreads();

    float acc[4][4];   // [batch j][gate g]
#pragma unroll
    for (int j = 0; j < 4; j++)
#pragma unroll
        for (int g = 0; g < 4; g++) acc[j][g] = 0.f;

#pragma unroll
    for (int s = 0; s < 4; s++) {
        if (s < 3) {
#pragma unroll
            for (int i = 0; i < 8; i++)
                xn[i] = *reinterpret_cast<const float4*>(
                    &XT[(size_t)(kbase + (s + 1) * 8 + i) * 128 + b0]);
        }
#pragma unroll
        for (int i = 0; i < 8; i += 4) {
            float wr[4][4];
#pragma unroll
            for (int g = 0; g < 4; g++)
                *reinterpret_cast<float4*>(wr[g]) =
                    *reinterpret_cast<const float4*>(&Ws[g * 256 + kbase + s * 8 + i]);
#pragma unroll
            for (int kk = 0; kk < 4; kk++) {
                float4 x = xv[i + kk];
#pragma unroll
                for (int g = 0; g < 4; g++) {
                    acc[0][g] = fmaf(x.x, wr[g][kk], acc[0][g]);
                    acc[1][g] = fmaf(x.y, wr[g][kk], acc[1][g]);
                    acc[2][g] = fmaf(x.z, wr[g][kk], acc[2][g]);
                    acc[3][g] = fmaf(x.w, wr[g][kk], acc[3][g]);
                }
            }
        }
        if (s < 3) {
#pragma unroll
            for (int i = 0; i < 8; i++) xv[i] = xn[i];
        }
    }

    __syncthreads();
#pragma unroll
    for (int g = 0; g < 4; g++)
#pragma unroll
        for (int j = 0; j < 4; j++)
            Rs[(g * 8 + warp) * 128 + b0 + j] = acc[j][g];
    __syncthreads();

    if (tid < 128) {
        const int b = tid;
        float gate[4];
#pragma unroll
        for (int g = 0; g < 4; g++) {
            float s = ggv[g];
#pragma unroll
            for (int w = 0; w < 8; w++)
                s += Rs[(g * 8 + w) * 128 + b];
            gate[g] = s;
        }
        float gi = sigmoidf_(gate[0]);
        float gf = sigmoidf_(gate[1]);
        float gg = tanhf(gate[2]);
        float go = sigmoidf_(gate[3]);
        float cn = fmaf(gf, cpv, gi * gg);
        float hn = go * tanhf(cn);

        if (LAYER == 1) {
            out[65536 + b * H_ + h] = cn;    // c1
            out[32768 + b * H_ + h] = hn;    // h1
            g_h1T[h * B_ + b] = hn;
        } else {
            out[131072 + b * H_ + h] = cn;   // c2
            out[98304 + b * H_ + h]  = hn;   // h2
            out[b * H_ + h]          = hn;   // outputs
        }
    }
}

// ---------------- launch ---------------------------------------------------------

extern "C" void kernel_launch(void* const* d_in, const int* in_sizes, int n_in,
                              void* d_out, int out_size)
{
    const float* embed   = (const float*)d_in[0];
    const float* enc     = (const float*)d_in[1];
    const float* hidden1 = (const float*)d_in[2];
    const float* cell1   = (const float*)d_in[3];
    const float* hidden2 = (const float*)d_in[4];
    const float* cell2   = (const float*)d_in[5];
    const float* w_ih1   = (const float*)d_in[6];
    const float* w_hh1   = (const float*)d_in[7];
    const float* b_ih1   = (const float*)d_in[8];
    const float* b_hh1   = (const float*)d_in[9];
    const float* w_ih2   = (const float*)d_in[10];
    const float* w_hh2   = (const float*)d_in[11];
    const float* b_ih2   = (const float*)d_in[12];
    const float* b_hh2   = (const float*)d_in[13];
    float* out = (float*)d_out;

    const int smem_mid = (8 * 512 + 64 * 128) * 4;   // 49152
    static bool attr_set = false;
    if (!attr_set) {
        cudaFuncSetAttribute(fused_mid,
            cudaFuncAttributeMaxDynamicSharedMemorySize, smem_mid);
        attr_set = true;
    }

    attn_kernel<<<ATTN_BLOCKS, 256>>>(enc, hidden1);
    fused_mid<<<384, 256, smem_mid>>>(
        hidden1, embed, hidden2,
        w_hh1, w_ih2, w_hh2, b_ih1, b_hh1, b_ih2, b_hh2);
    finish_kernel<1><<<256, 256>>>(w_ih1, cell1, out);
    finish_kernel<2><<<256, 256>>>(w_ih2, cell2, out);
}

// round 8
// speedup vs baseline: 1.2053x; 1.2053x over previous
#include <cuda_runtime.h>

// ---------------------------------------------------------------------------
// Decoder step: attention (B=128, L=2048, H=256) + 2x LSTM cell.
//
// attn_kernel : split-K flash softmax, grid = 128 x 4 splits (HBM-bound).
//               Fused extras:
//                 - sp=0/1/2 blocks write transposed hidden1 / embed /
//                   hidden2 rows into g_X1T / g_X2T (k-major, coalesced for
//                   the LSTM GEMMs).
//                 - last-arriving split block per batch (atomic counter)
//                   merges the 4 online-softmax partials and writes the ctx
//                   rows of g_X1T. Counter self-resets for graph replay.
// lstm_full<1>: gates = bias + [ctx;h_prev] @ [w_ih1|w_hh1]^T  (K=512),
//               epilogue -> h1,c1, h1T rows of g_X2T.
// lstm_full<2>: gates = bias + [embed;h1;hidden2] @ [w_ih2|w_hh2]^T (K=768),
//               epilogue -> outputs,h2,c2.
//               Both: grid=256 (1 h = 4 gate rows/block), warps split K
//               8-ways, X via pipelined coalesced LDG.128, W via cp.async.
// ---------------------------------------------------------------------------

#define B_ 128
#define H_ 256
#define L_ 2048
#define NSPLIT 4
#define LSP (L_ / NSPLIT)
#define ATTN_BLOCKS (B_ * NSPLIT)   // 512

__device__ float g_X1T[512 * 128];   // rows 0-255 ctx, 256-511 hidden1
__device__ float g_X2T[768 * 128];   // rows 0-255 embed, 256-511 h1, 512-767 hidden2
__device__ float g_ctx_part[B_ * NSPLIT * H_];
__device__ float g_md[B_ * NSPLIT * 2];
__device__ unsigned g_cnt[B_];       // zero-init; self-resetting

// ---------------- helpers ----------------------------------------------------

__device__ __forceinline__ void online_step(
    const float4& ea, const float4& eb, const float4& ha, const float4& hb,
    float& m, float& d, float* c)
{
    float s = ea.x * ha.x + ea.y * ha.y + ea.z * ha.z + ea.w * ha.w
            + eb.x * hb.x + eb.y * hb.y + eb.z * hb.z + eb.w * hb.w;
#pragma unroll
    for (int off = 16; off; off >>= 1)
        s += __shfl_xor_sync(0xffffffffu, s, off);
    float mn = fmaxf(m, s);
    float es = __expf(s - mn);
    float em = __expf(m - mn);
    d = d * em + es;
    c[0] = fmaf(c[0], em, es * ea.x);
    c[1] = fmaf(c[1], em, es * ea.y);
    c[2] = fmaf(c[2], em, es * ea.z);
    c[3] = fmaf(c[3], em, es * ea.w);
    c[4] = fmaf(c[4], em, es * eb.x);
    c[5] = fmaf(c[5], em, es * eb.y);
    c[6] = fmaf(c[6], em, es * eb.z);
    c[7] = fmaf(c[7], em, es * eb.w);
    m = mn;
}

__device__ __forceinline__ float sigmoidf_(float x) {
    return 1.f / (1.f + __expf(-x));
}

__device__ __forceinline__ void cp_async16(void* smem_dst, const void* gmem_src) {
    unsigned saddr = (unsigned)__cvta_generic_to_shared(smem_dst);
    asm volatile("cp.async.cg.shared.global [%0], [%1], 16;\n"
                 :: "r"(saddr), "l"(gmem_src));
}
__device__ __forceinline__ void cp_commit() {
    asm volatile("cp.async.commit_group;\n");
}
__device__ __forceinline__ void cp_wait0() {
    asm volatile("cp.async.wait_group 0;\n");
}

// ---------------- attention + fused combine/pack -------------------------------

__global__ __launch_bounds__(256, 2) void attn_kernel(
    const float* __restrict__ enc,
    const float* __restrict__ hidden1,
    const float* __restrict__ embed,
    const float* __restrict__ hidden2)
{
    const int bx   = blockIdx.x;
    const int tid  = threadIdx.x;
    const int w    = tid >> 5;
    const int lane = tid & 31;

    const int b  = bx >> 2;
    const int sp = bx & 3;

    __shared__ float h1s[H_];
    __shared__ float ctx_s[8][H_];
    __shared__ float m_s[8], d_s[8];
    __shared__ unsigned old_s;

    h1s[tid] = hidden1[b * H_ + tid];

    // pack transposed static rows (tiny, overlapped with mainloop latency)
    if (sp == 1) g_X2T[tid * B_ + b]          = embed[b * H_ + tid];
    if (sp == 2) g_X2T[(512 + tid) * B_ + b]  = hidden2[b * H_ + tid];
    __syncthreads();
    if (sp == 0) g_X1T[(H_ + tid) * B_ + b]   = h1s[tid];

    const float4 ha = *reinterpret_cast<const float4*>(&h1s[lane * 4]);
    const float4 hb = *reinterpret_cast<const float4*>(&h1s[128 + lane * 4]);

    const float* encb = enc + (size_t)b * (L_ * H_) + (size_t)sp * (LSP * H_);

    float m[4], d[4], c[4][8];
    float4 ea[4], eb[4];
    const float* p[4];
#pragma unroll
    for (int j = 0; j < 4; j++) {
        m[j] = -1e30f; d[j] = 0.f;
#pragma unroll
        for (int q = 0; q < 8; q++) c[j][q] = 0.f;
        p[j]  = encb + (size_t)(w + 8 * j) * H_ + lane * 4;
        ea[j] = *reinterpret_cast<const float4*>(p[j]);
        eb[j] = *reinterpret_cast<const float4*>(p[j] + 128);
    }

    const int STRIDE = 32 * H_;
    const int ITERS  = LSP / 32;
    for (int i = 0; i < ITERS - 1; i++) {
        float4 na[4], nb[4];
#pragma unroll
        for (int j = 0; j < 4; j++) {
            na[j] = *reinterpret_cast<const float4*>(p[j] + STRIDE);
            nb[j] = *reinterpret_cast<const float4*>(p[j] + STRIDE + 128);
        }
#pragma unroll
        for (int j = 0; j < 4; j++)
            online_step(ea[j], eb[j], ha, hb, m[j], d[j], c[j]);
#pragma unroll
        for (int j = 0; j < 4; j++) {
            ea[j] = na[j]; eb[j] = nb[j]; p[j] += STRIDE;
        }
    }
#pragma unroll
    for (int j = 0; j < 4; j++)
        online_step(ea[j], eb[j], ha, hb, m[j], d[j], c[j]);

#pragma unroll
    for (int j = 1; j < 4; j++) {
        float M2 = fmaxf(m[0], m[j]);
        float e0 = __expf(m[0] - M2);
        float e1 = __expf(m[j] - M2);
        d[0] = d[0] * e0 + d[j] * e1;
#pragma unroll
        for (int q = 0; q < 8; q++)
            c[0][q] = c[0][q] * e0 + c[j][q] * e1;
        m[0] = M2;
    }

#pragma unroll
    for (int q = 0; q < 4; q++) {
        ctx_s[w][lane * 4 + q]       = c[0][q];
        ctx_s[w][128 + lane * 4 + q] = c[0][4 + q];
    }
    if (lane == 0) { m_s[w] = m[0]; d_s[w] = d[0]; }
    __syncthreads();

    float M = m_s[0];
#pragma unroll
    for (int ww = 1; ww < 8; ww++) M = fmaxf(M, m_s[ww]);
    float D = 0.f, C = 0.f;
#pragma unroll
    for (int ww = 0; ww < 8; ww++) {
        float e = __expf(m_s[ww] - M);
        D += d_s[ww] * e;
        C += ctx_s[ww][tid] * e;
    }
    g_ctx_part[bx * H_ + tid] = C;
    if (tid == 0) { g_md[bx * 2] = M; g_md[bx * 2 + 1] = D; }

    // ---- last-arriver combine (threadfence reduction pattern) ----
    __threadfence();
    __syncthreads();
    if (tid == 0) old_s = atomicAdd(&g_cnt[b], 1u);
    __syncthreads();
    if (old_s == NSPLIT - 1) {
        __threadfence();
        float ms[NSPLIT], ds[NSPLIT];
#pragma unroll
        for (int s = 0; s < NSPLIT; s++) {
            ms[s] = g_md[(b * NSPLIT + s) * 2];
            ds[s] = g_md[(b * NSPLIT + s) * 2 + 1];
        }
        float MM = ms[0];
#pragma unroll
        for (int s = 1; s < NSPLIT; s++) MM = fmaxf(MM, ms[s]);
        float DD = 0.f, CC = 0.f;
#pragma unroll
        for (int s = 0; s < NSPLIT; s++) {
            float e = __expf(ms[s] - MM);
            DD += ds[s] * e;
            CC += g_ctx_part[(b * NSPLIT + s) * H_ + tid] * e;
        }
        g_X1T[tid * B_ + b] = CC / DD;
        if (tid == 0) g_cnt[b] = 0u;   // reset for next graph replay
    }
}

// ---------------- full-K LSTM cell ----------------------------------------------

// Block = 1 h-index (4 gate rows) x 128 batches, grid = 256.
// Warps split K 8-ways. X = g_X?T (k-major), pipelined coalesced LDG.128.
template <int LAYER>
__global__ __launch_bounds__(256, 2) void lstm_full(
    const float* __restrict__ w_ih, const float* __restrict__ w_hh,
    const float* __restrict__ b_ih, const float* __restrict__ b_hh,
    const float* __restrict__ c_prev,
    float* __restrict__ out)
{
    constexpr int K   = (LAYER == 1) ? 512 : 768;
    constexpr int KIH = (LAYER == 1) ? 256 : 512;   // w_ih column count
    constexpr int KW  = K / 8;                      // per-warp k: 64 / 96
    constexpr int NS  = KW / 8;                     // 8-k stages: 8 / 12

    __shared__ float Ws[4 * K];
    __shared__ float Rs[4 * 8 * 128];

    const int tid  = threadIdx.x;
    const int warp = tid >> 5;
    const int lane = tid & 31;
    const int b0   = lane * 4;
    const int h    = blockIdx.x;

    const float* __restrict__ XT = (LAYER == 1) ? g_X1T : g_X2T;

    // epilogue operand prefetch
    float bias[4];
    float cpv = 0.f;
    if (tid < 128) {
#pragma unroll
        for (int g = 0; g < 4; g++)
            bias[g] = b_ih[g * H_ + h] + b_hh[g * H_ + h];
        cpv = c_prev[tid * H_ + h];
    }

    const int kbase = warp * KW;

    // issue first X batch before W prologue
    float4 xv[8], xn[8];
#pragma unroll
    for (int i = 0; i < 8; i++)
        xv[i] = *reinterpret_cast<const float4*>(
            &XT[(size_t)(kbase + i) * 128 + b0]);

    // W prologue: 4 rows x K/4 float4 via cp.async
    for (int t = tid; t < K; t += 256) {
        int r = t / (K / 4);
        int k = (t % (K / 4)) * 4;
        const float* src = (k < KIH)
            ? &w_ih[(size_t)(r * H_ + h) * KIH + k]
            : &w_hh[(size_t)(r * H_ + h) * 256 + (k - KIH)];
        cp_async16(&Ws[r * K + k], src);
    }
    cp_commit();
    cp_wait0();
    __syncthreads();

    float acc[4][4];   // [batch j][gate g]
#pragma unroll
    for (int j = 0; j < 4; j++)
#pragma unroll
        for (int g = 0; g < 4; g++) acc[j][g] = 0.f;

#pragma unroll
    for (int s = 0; s < NS; s++) {
        if (s + 1 < NS) {
#pragma unroll
            for (int i = 0; i < 8; i++)
                xn[i] = *reinterpret_cast<const float4*>(
                    &XT[(size_t)(kbase + (s + 1) * 8 + i) * 128 + b0]);
        }
#pragma unroll
        for (int i = 0; i < 8; i += 4) {
            float wr[4][4];
#pragma unroll
            for (int g = 0; g < 4; g++)
                *reinterpret_cast<float4*>(wr[g]) =
                    *reinterpret_cast<const float4*>(&Ws[g * K + kbase + s * 8 + i]);
#pragma unroll
            for (int kk = 0; kk < 4; kk++) {
                float4 x = xv[i + kk];
#pragma unroll
                for (int g = 0; g < 4; g++) {
                    acc[0][g] = fmaf(x.x, wr[g][kk], acc[0][g]);
                    acc[1][g] = fmaf(x.y, wr[g][kk], acc[1][g]);
                    acc[2][g] = fmaf(x.z, wr[g][kk], acc[2][g]);
                    acc[3][g] = fmaf(x.w, wr[g][kk], acc[3][g]);
                }
            }
        }
        if (s + 1 < NS) {
#pragma unroll
            for (int i = 0; i < 8; i++) xv[i] = xn[i];
        }
    }

    __syncthreads();
#pragma unroll
    for (int g = 0; g < 4; g++)
#pragma unroll
        for (int j = 0; j < 4; j++)
            Rs[(g * 8 + warp) * 128 + b0 + j] = acc[j][g];
    __syncthreads();

    if (tid < 128) {
        const int b = tid;
        float gate[4];
#pragma unroll
        for (int g = 0; g < 4; g++) {
            float s = bias[g];
#pragma unroll
            for (int w = 0; w < 8; w++)
                s += Rs[(g * 8 + w) * 128 + b];
            gate[g] = s;
        }
        float gi = sigmoidf_(gate[0]);
        float gf = sigmoidf_(gate[1]);
        float gg = tanhf(gate[2]);
        float go = sigmoidf_(gate[3]);
        float cn = fmaf(gf, cpv, gi * gg);
        float hn = go * tanhf(cn);

        if (LAYER == 1) {
            out[65536 + b * H_ + h] = cn;    // c1
            out[32768 + b * H_ + h] = hn;    // h1
            g_X2T[(H_ + h) * B_ + b] = hn;   // h1T for lstm2 (coalesced)
        } else {
            out[131072 + b * H_ + h] = cn;   // c2
            out[98304 + b * H_ + h]  = hn;   // h2
            out[b * H_ + h]          = hn;   // outputs
        }
    }
}

// ---------------- launch ----------------------------------------------------------

extern "C" void kernel_launch(void* const* d_in, const int* in_sizes, int n_in,
                              void* d_out, int out_size)
{
    const float* embed   = (const float*)d_in[0];
    const float* enc     = (const float*)d_in[1];
    const float* hidden1 = (const float*)d_in[2];
    const float* cell1   = (const float*)d_in[3];
    const float* hidden2 = (const float*)d_in[4];
    const float* cell2   = (const float*)d_in[5];
    const float* w_ih1   = (const float*)d_in[6];
    const float* w_hh1   = (const float*)d_in[7];
    const float* b_ih1   = (const float*)d_in[8];
    const float* b_hh1   = (const float*)d_in[9];
    const float* w_ih2   = (const float*)d_in[10];
    const float* w_hh2   = (const float*)d_in[11];
    const float* b_ih2   = (const float*)d_in[12];
    const float* b_hh2   = (const float*)d_in[13];
    float* out = (float*)d_out;

    attn_kernel<<<ATTN_BLOCKS, 256>>>(enc, hidden1, embed, hidden2);
    lstm_full<1><<<256, 256>>>(w_ih1, w_hh1, b_ih1, b_hh1, cell1, out);
    lstm_full<2><<<256, 256>>>(w_ih2, w_hh2, b_ih2, b_hh2, cell2, out);
}